// round 8
// baseline (speedup 1.0000x reference)
#include <cuda_runtime.h>
#include <cuda_bf16.h>
#include <stdint.h>
#include <math.h>

// ---------------------------------------------------------------------------
// NeuronBloomBlock: B=2, S=2048, D=2048, H=16, HD=128, FF=8192, fp32.
// R8: tf32 GEMM with double-buffered smem + register prefetch, 256 thr/CTA.
// ---------------------------------------------------------------------------

#define NTOK   4096
#define DMODEL 2048
#define DQKV   6144
#define DFF    8192
#define SEQ    2048
#define NHEAD  16
#define HEADD  128
#define LNEPS  1e-5f

#define OFF_H    ((size_t)0)
#define OFF_QKV  ((size_t)8388608)
#define OFF_ATTN ((size_t)(8388608 + 25165824))
#define OFF_X1   ((size_t)(8388608 + 25165824 + 8388608))
#define OFF_FF   ((size_t)(8388608 + 25165824 + 8388608 + 8388608))
#define SCRATCH_FLOATS ((size_t)(8388608 + 25165824 + 8388608 + 8388608 + 33554432))

__device__ float g_scratch[SCRATCH_FLOATS];

// ---------------------------------------------------------------------------
// LayerNorm: one block per row (D=2048), 256 threads, 8 elems/thread.
// ---------------------------------------------------------------------------
__global__ void ln_kernel(const float* __restrict__ x, const float* __restrict__ w,
                          const float* __restrict__ bb, float* __restrict__ out) {
    __shared__ float red[8];
    __shared__ float stat[2];
    int row = blockIdx.x;
    int tid = threadIdx.x;
    const float* xr = x + (size_t)row * DMODEL;

    float4 a = *(const float4*)(xr + tid * 4);
    float4 b = *(const float4*)(xr + 1024 + tid * 4);

    float s = a.x + a.y + a.z + a.w + b.x + b.y + b.z + b.w;
    #pragma unroll
    for (int o = 16; o; o >>= 1) s += __shfl_xor_sync(0xffffffffu, s, o);
    if ((tid & 31) == 0) red[tid >> 5] = s;
    __syncthreads();
    if (tid < 8) {
        float t = red[tid];
        #pragma unroll
        for (int o = 4; o; o >>= 1) t += __shfl_xor_sync(0xffu, t, o);
        if (tid == 0) stat[0] = t;
    }
    __syncthreads();
    float mean = stat[0] * (1.0f / (float)DMODEL);

    float dx0 = a.x - mean, dx1 = a.y - mean, dx2 = a.z - mean, dx3 = a.w - mean;
    float dy0 = b.x - mean, dy1 = b.y - mean, dy2 = b.z - mean, dy3 = b.w - mean;
    float s2 = dx0*dx0 + dx1*dx1 + dx2*dx2 + dx3*dx3
             + dy0*dy0 + dy1*dy1 + dy2*dy2 + dy3*dy3;
    __syncthreads();
    #pragma unroll
    for (int o = 16; o; o >>= 1) s2 += __shfl_xor_sync(0xffffffffu, s2, o);
    if ((tid & 31) == 0) red[tid >> 5] = s2;
    __syncthreads();
    if (tid < 8) {
        float t = red[tid];
        #pragma unroll
        for (int o = 4; o; o >>= 1) t += __shfl_xor_sync(0xffu, t, o);
        if (tid == 0) stat[1] = t;
    }
    __syncthreads();
    float inv = rsqrtf(stat[1] * (1.0f / (float)DMODEL) + LNEPS);

    float4 w0 = *(const float4*)(w + tid * 4);
    float4 w1 = *(const float4*)(w + 1024 + tid * 4);
    float4 g0 = *(const float4*)(bb + tid * 4);
    float4 g1 = *(const float4*)(bb + 1024 + tid * 4);

    float* orow = out + (size_t)row * DMODEL;
    float4 r0, r1;
    r0.x = dx0 * inv * w0.x + g0.x; r0.y = dx1 * inv * w0.y + g0.y;
    r0.z = dx2 * inv * w0.z + g0.z; r0.w = dx3 * inv * w0.w + g0.w;
    r1.x = dy0 * inv * w1.x + g1.x; r1.y = dy1 * inv * w1.y + g1.y;
    r1.z = dy2 * inv * w1.z + g1.z; r1.w = dy3 * inv * w1.w + g1.w;
    *(float4*)(orow + tid * 4) = r0;
    *(float4*)(orow + 1024 + tid * 4) = r1;
}

// ---------------------------------------------------------------------------
// TF32 tensor-core GEMM, double-buffered.
// Block 128x128, K-tile 32, 256 threads = 8 warps (2x4), warp tile 64x32.
// ---------------------------------------------------------------------------
#define EPI_BIAS      0
#define EPI_BIAS_RES  1
#define EPI_BIAS_GELU 2

__device__ __forceinline__ float gelu_tanh(float v) {
    float t = tanhf(0.7978845608028654f * (v + 0.044715f * v * v * v));
    return 0.5f * v * (1.0f + t);
}

__device__ __forceinline__ unsigned int f2tf32(float x) {
    unsigned int y;
    asm("cvt.rna.tf32.f32 %0, %1;" : "=r"(y) : "f"(x));
    return y;
}

__device__ __forceinline__ float4 cvt4(float4 v) {
    float4 t;
    t.x = __uint_as_float(f2tf32(v.x));
    t.y = __uint_as_float(f2tf32(v.y));
    t.z = __uint_as_float(f2tf32(v.z));
    t.w = __uint_as_float(f2tf32(v.w));
    return t;
}

__device__ __forceinline__ void mma_tf32(float c[4],
        unsigned int a0, unsigned int a1, unsigned int a2, unsigned int a3,
        unsigned int b0, unsigned int b1) {
    asm volatile(
        "mma.sync.aligned.m16n8k8.row.col.f32.tf32.tf32.f32 "
        "{%0,%1,%2,%3}, {%4,%5,%6,%7}, {%8,%9}, {%0,%1,%2,%3};\n"
        : "+f"(c[0]), "+f"(c[1]), "+f"(c[2]), "+f"(c[3])
        : "r"(a0), "r"(a1), "r"(a2), "r"(a3), "r"(b0), "r"(b1));
}

// smem layout (floats): A buffers 2 x 128 x 36, then B buffers 2 x 32 x 136.
#define ASZ (128 * 36)
#define BSZ (32 * 136)
#define GSMEM_BYTES ((2 * ASZ + 2 * BSZ) * 4)
#define AS(buf, r, k) sm[(buf) * ASZ + (r) * 36 + (k)]
#define BS(buf, r, c) sm[2 * ASZ + (buf) * BSZ + (r) * 136 + (c)]

template<int EPI>
__global__ __launch_bounds__(256)
void tgemm_kernel(const float* __restrict__ A, const float* __restrict__ W,
                  const float* __restrict__ bias, const float* __restrict__ res,
                  float* __restrict__ C, int M, int N, int K) {
    extern __shared__ float sm[];

    int tid = threadIdx.x;
    int lane = tid & 31;
    int wid  = tid >> 5;
    int warp_m = wid & 1;           // 0..1  (64-row slab)
    int warp_n = wid >> 1;          // 0..3  (32-col slab)
    int bm = blockIdx.y * 128;
    int bn = blockIdx.x * 128;

    int lr = lane >> 2;   // 0..7
    int lc = lane & 3;    // 0..3

    float acc[4][4][4];
    #pragma unroll
    for (int mt = 0; mt < 4; ++mt)
        #pragma unroll
        for (int nt = 0; nt < 4; ++nt)
            #pragma unroll
            for (int r = 0; r < 4; ++r) acc[mt][nt][r] = 0.0f;

    // per-thread load coords (constant across tiles)
    int ar[4], ak[4], br[4], bc[4];
    #pragma unroll
    for (int u = 0; u < 4; ++u) {
        int idx = tid + u * 256;          // 0..1023 float4 slots
        ar[u] = idx >> 3;                 // A row 0..127
        ak[u] = (idx & 7) << 2;           // A k4
        br[u] = idx >> 5;                 // B k-row 0..31
        bc[u] = (idx & 31) << 2;          // B col4
    }

    float4 areg[4], breg[4];

    // prologue: load tile 0
    #pragma unroll
    for (int u = 0; u < 4; ++u) {
        areg[u] = *(const float4*)(A + (size_t)(bm + ar[u]) * K + ak[u]);
        breg[u] = *(const float4*)(W + (size_t)br[u] * N + bn + bc[u]);
    }
    #pragma unroll
    for (int u = 0; u < 4; ++u) {
        float4 t = cvt4(areg[u]);
        AS(0, ar[u], ak[u] + 0) = t.x;
        AS(0, ar[u], ak[u] + 1) = t.y;
        AS(0, ar[u], ak[u] + 2) = t.z;
        AS(0, ar[u], ak[u] + 3) = t.w;
        *(float4*)&BS(0, br[u], bc[u]) = cvt4(breg[u]);
    }
    __syncthreads();

    int nk = K >> 5;
    for (int kt = 0; kt < nk; ++kt) {
        int cur = kt & 1;
        int nxt = cur ^ 1;
        // prefetch next tile into registers (overlaps with mma below)
        if (kt + 1 < nk) {
            int k0 = (kt + 1) << 5;
            #pragma unroll
            for (int u = 0; u < 4; ++u) {
                areg[u] = *(const float4*)(A + (size_t)(bm + ar[u]) * K + k0 + ak[u]);
                breg[u] = *(const float4*)(W + (size_t)(k0 + br[u]) * N + bn + bc[u]);
            }
        }

        // compute on current buffer
        #pragma unroll
        for (int ks = 0; ks < 4; ++ks) {
            unsigned int af[4][4];
            #pragma unroll
            for (int mt = 0; mt < 4; ++mt) {
                int row = warp_m * 64 + mt * 16 + lr;
                int col = ks * 8 + lc;
                af[mt][0] = __float_as_uint(AS(cur, row, col));
                af[mt][1] = __float_as_uint(AS(cur, row + 8, col));
                af[mt][2] = __float_as_uint(AS(cur, row, col + 4));
                af[mt][3] = __float_as_uint(AS(cur, row + 8, col + 4));
            }
            unsigned int bf[4][2];
            #pragma unroll
            for (int nt = 0; nt < 4; ++nt) {
                int ncol = warp_n * 32 + nt * 8 + lr;
                int krow = ks * 8 + lc;
                bf[nt][0] = __float_as_uint(BS(cur, krow, ncol));
                bf[nt][1] = __float_as_uint(BS(cur, krow + 4, ncol));
            }
            #pragma unroll
            for (int mt = 0; mt < 4; ++mt)
                #pragma unroll
                for (int nt = 0; nt < 4; ++nt)
                    mma_tf32(acc[mt][nt], af[mt][0], af[mt][1], af[mt][2], af[mt][3],
                             bf[nt][0], bf[nt][1]);
        }

        // stage next tile to the other buffer
        if (kt + 1 < nk) {
            #pragma unroll
            for (int u = 0; u < 4; ++u) {
                float4 t = cvt4(areg[u]);
                AS(nxt, ar[u], ak[u] + 0) = t.x;
                AS(nxt, ar[u], ak[u] + 1) = t.y;
                AS(nxt, ar[u], ak[u] + 2) = t.z;
                AS(nxt, ar[u], ak[u] + 3) = t.w;
                *(float4*)&BS(nxt, br[u], bc[u]) = cvt4(breg[u]);
            }
            __syncthreads();
        }
    }

    // ---- epilogue ----
    #pragma unroll
    for (int mt = 0; mt < 4; ++mt) {
        int gr0 = bm + warp_m * 64 + mt * 16 + lr;
        int gr1 = gr0 + 8;
        #pragma unroll
        for (int nt = 0; nt < 4; ++nt) {
            int gc = bn + warp_n * 32 + nt * 8 + (lc << 1);
            float2 bv = *(const float2*)(bias + gc);
            float2 v0, v1;
            v0.x = acc[mt][nt][0] + bv.x; v0.y = acc[mt][nt][1] + bv.y;
            v1.x = acc[mt][nt][2] + bv.x; v1.y = acc[mt][nt][3] + bv.y;
            if (EPI == EPI_BIAS_RES) {
                float2 r0 = *(const float2*)(res + (size_t)gr0 * N + gc);
                float2 r1 = *(const float2*)(res + (size_t)gr1 * N + gc);
                v0.x += r0.x; v0.y += r0.y;
                v1.x += r1.x; v1.y += r1.y;
            }
            if (EPI == EPI_BIAS_GELU) {
                v0.x = gelu_tanh(v0.x); v0.y = gelu_tanh(v0.y);
                v1.x = gelu_tanh(v1.x); v1.y = gelu_tanh(v1.y);
            }
            *(float2*)(C + (size_t)gr0 * N + gc) = v0;
            *(float2*)(C + (size_t)gr1 * N + gc) = v1;
        }
    }
}

// ---------------------------------------------------------------------------
// Flash attention (fp32) with ALiBi + causal mask. (unchanged)
// ---------------------------------------------------------------------------
#define AT_SMEM ((3 * 64 * 132 + 64 * 68) * 4)

__global__ __launch_bounds__(256)
void attn_kernel(const float* __restrict__ qkv, float* __restrict__ out) {
    extern __shared__ float sm[];
    float* Qs = sm;                  // [64][132]
    float* Ks = sm + 64 * 132;       // [64][132]
    float* Vs = sm + 2 * 64 * 132;   // [64][132]
    float* Ps = sm + 3 * 64 * 132;   // [64][68]

    int tid = threadIdx.x;
    int tx = tid & 15, ty = tid >> 4;
    int qt = blockIdx.x, h = blockIdx.y, b = blockIdx.z;
    int q0 = qt * 64;

    const float scale = 0.08838834764831845f;   // 1/sqrt(128)
    float slope = exp2f(-0.5f * (float)(h + 1));

    const float* qbase = qkv + (size_t)b * SEQ * DQKV + (size_t)h * HEADD;
    const float* kbase = qbase + DMODEL;
    const float* vbase = qbase + 2 * DMODEL;

    for (int i = tid; i < 64 * 32; i += 256) {
        int r = i >> 5, c4 = (i & 31) << 2;
        float4 v = *(const float4*)(qbase + (size_t)(q0 + r) * DQKV + c4);
        Qs[r * 132 + c4 + 0] = v.x * scale;
        Qs[r * 132 + c4 + 1] = v.y * scale;
        Qs[r * 132 + c4 + 2] = v.z * scale;
        Qs[r * 132 + c4 + 3] = v.w * scale;
    }

    float m_i[4], l_i[4], acc[4][8];
    #pragma unroll
    for (int i = 0; i < 4; ++i) {
        m_i[i] = -INFINITY; l_i[i] = 0.0f;
        #pragma unroll
        for (int c = 0; c < 8; ++c) acc[i][c] = 0.0f;
    }

    int nkb = qt + 1;
    for (int kb = 0; kb < nkb; ++kb) {
        __syncthreads();
        for (int i = tid; i < 64 * 32; i += 256) {
            int r = i >> 5, c4 = (i & 31) << 2;
            *(float4*)&Ks[r * 132 + c4] =
                *(const float4*)(kbase + (size_t)(kb * 64 + r) * DQKV + c4);
            *(float4*)&Vs[r * 132 + c4] =
                *(const float4*)(vbase + (size_t)(kb * 64 + r) * DQKV + c4);
        }
        __syncthreads();

        float s[4][4];
        #pragma unroll
        for (int i = 0; i < 4; ++i)
            #pragma unroll
            for (int j = 0; j < 4; ++j) s[i][j] = 0.0f;

        for (int d4 = 0; d4 < 32; ++d4) {
            float4 qv[4], kv[4];
            #pragma unroll
            for (int i = 0; i < 4; ++i)
                qv[i] = *(const float4*)&Qs[(ty * 4 + i) * 132 + d4 * 4];
            #pragma unroll
            for (int j = 0; j < 4; ++j)
                kv[j] = *(const float4*)&Ks[(j * 16 + tx) * 132 + d4 * 4];
            #pragma unroll
            for (int i = 0; i < 4; ++i)
                #pragma unroll
                for (int j = 0; j < 4; ++j) {
                    s[i][j] = fmaf(qv[i].x, kv[j].x, s[i][j]);
                    s[i][j] = fmaf(qv[i].y, kv[j].y, s[i][j]);
                    s[i][j] = fmaf(qv[i].z, kv[j].z, s[i][j]);
                    s[i][j] = fmaf(qv[i].w, kv[j].w, s[i][j]);
                }
        }

        bool diag = (kb == qt);
        float a4[4];
        #pragma unroll
        for (int i = 0; i < 4; ++i) {
            int gr = q0 + ty * 4 + i;
            float rowmax = -1e30f;
            #pragma unroll
            for (int j = 0; j < 4; ++j) {
                int gc = kb * 64 + j * 16 + tx;
                float val = s[i][j] + slope * (float)(gc - gr);
                if (diag && gc > gr) val = -1e30f;
                s[i][j] = val;
                rowmax = fmaxf(rowmax, val);
            }
            #pragma unroll
            for (int o = 8; o; o >>= 1)
                rowmax = fmaxf(rowmax, __shfl_xor_sync(0xffffffffu, rowmax, o, 16));
            float mnew = fmaxf(m_i[i], rowmax);
            float alpha = expf(m_i[i] - mnew);
            float rowsum = 0.0f;
            #pragma unroll
            for (int j = 0; j < 4; ++j) {
                float p = expf(s[i][j] - mnew);
                s[i][j] = p;
                rowsum += p;
            }
            #pragma unroll
            for (int o = 8; o; o >>= 1)
                rowsum += __shfl_xor_sync(0xffffffffu, rowsum, o, 16);
            l_i[i] = l_i[i] * alpha + rowsum;
            m_i[i] = mnew;
            a4[i] = alpha;
        }

        #pragma unroll
        for (int i = 0; i < 4; ++i)
            #pragma unroll
            for (int j = 0; j < 4; ++j)
                Ps[(ty * 4 + i) * 68 + j * 16 + tx] = s[i][j];
        __syncthreads();

        #pragma unroll
        for (int i = 0; i < 4; ++i)
            #pragma unroll
            for (int c = 0; c < 8; ++c) acc[i][c] *= a4[i];

        #pragma unroll 4
        for (int k = 0; k < 64; ++k) {
            float4 v0 = *(const float4*)&Vs[k * 132 + tx * 4];
            float4 v1 = *(const float4*)&Vs[k * 132 + 64 + tx * 4];
            #pragma unroll
            for (int i = 0; i < 4; ++i) {
                float p = Ps[(ty * 4 + i) * 68 + k];
                acc[i][0] = fmaf(p, v0.x, acc[i][0]);
                acc[i][1] = fmaf(p, v0.y, acc[i][1]);
                acc[i][2] = fmaf(p, v0.z, acc[i][2]);
                acc[i][3] = fmaf(p, v0.w, acc[i][3]);
                acc[i][4] = fmaf(p, v1.x, acc[i][4]);
                acc[i][5] = fmaf(p, v1.y, acc[i][5]);
                acc[i][6] = fmaf(p, v1.z, acc[i][6]);
                acc[i][7] = fmaf(p, v1.w, acc[i][7]);
            }
        }
    }

    #pragma unroll
    for (int i = 0; i < 4; ++i) {
        float inv = 1.0f / l_i[i];
        size_t orow = ((size_t)(b * SEQ + q0 + ty * 4 + i)) * DMODEL + h * HEADD;
        float4 o0, o1;
        o0.x = acc[i][0] * inv; o0.y = acc[i][1] * inv;
        o0.z = acc[i][2] * inv; o0.w = acc[i][3] * inv;
        o1.x = acc[i][4] * inv; o1.y = acc[i][5] * inv;
        o1.z = acc[i][6] * inv; o1.w = acc[i][7] * inv;
        *(float4*)(out + orow + tx * 4) = o0;
        *(float4*)(out + orow + 64 + tx * 4) = o1;
    }
}

// ---------------------------------------------------------------------------
extern "C" void kernel_launch(void* const* d_in, const int* in_sizes, int n_in,
                              void* d_out, int out_size) {
    const float* x     = (const float*)d_in[0];
    const float* ln1_w = (const float*)d_in[1];
    const float* ln1_b = (const float*)d_in[2];
    const float* wqkv  = (const float*)d_in[3];
    const float* bqkv  = (const float*)d_in[4];
    const float* wo    = (const float*)d_in[5];
    const float* bo    = (const float*)d_in[6];
    const float* ln2_w = (const float*)d_in[7];
    const float* ln2_b = (const float*)d_in[8];
    const float* w1    = (const float*)d_in[9];
    const float* b1    = (const float*)d_in[10];
    const float* w2    = (const float*)d_in[11];
    const float* b2    = (const float*)d_in[12];
    float* out = (float*)d_out;

    float* base = nullptr;
    cudaGetSymbolAddress((void**)&base, g_scratch);
    float* h    = base + OFF_H;
    float* qkv  = base + OFF_QKV;
    float* attn = base + OFF_ATTN;
    float* x1   = base + OFF_X1;
    float* ff   = base + OFF_FF;

    cudaFuncSetAttribute(attn_kernel, cudaFuncAttributeMaxDynamicSharedMemorySize, AT_SMEM);
    cudaFuncSetAttribute(tgemm_kernel<EPI_BIAS>,
                         cudaFuncAttributeMaxDynamicSharedMemorySize, GSMEM_BYTES);
    cudaFuncSetAttribute(tgemm_kernel<EPI_BIAS_RES>,
                         cudaFuncAttributeMaxDynamicSharedMemorySize, GSMEM_BYTES);
    cudaFuncSetAttribute(tgemm_kernel<EPI_BIAS_GELU>,
                         cudaFuncAttributeMaxDynamicSharedMemorySize, GSMEM_BYTES);

    // 1. h = LN1(x)
    ln_kernel<<<NTOK, 256>>>(x, ln1_w, ln1_b, h);
    // 2. qkv = h @ wqkv + bqkv
    tgemm_kernel<EPI_BIAS><<<dim3(DQKV / 128, NTOK / 128), 256, GSMEM_BYTES>>>(
        h, wqkv, bqkv, nullptr, qkv, NTOK, DQKV, DMODEL);
    // 3. attention
    attn_kernel<<<dim3(SEQ / 64, NHEAD, 2), 256, AT_SMEM>>>(qkv, attn);
    // 4. x1 = x + attn @ wo + bo
    tgemm_kernel<EPI_BIAS_RES><<<dim3(DMODEL / 128, NTOK / 128), 256, GSMEM_BYTES>>>(
        attn, wo, bo, x, x1, NTOK, DMODEL, DMODEL);
    // 5. h = LN2(x1)
    ln_kernel<<<NTOK, 256>>>(x1, ln2_w, ln2_b, h);
    // 6. ff = gelu(h @ w1 + b1)
    tgemm_kernel<EPI_BIAS_GELU><<<dim3(DFF / 128, NTOK / 128), 256, GSMEM_BYTES>>>(
        h, w1, b1, nullptr, ff, NTOK, DFF, DMODEL);
    // 7. out = x1 + ff @ w2 + b2
    tgemm_kernel<EPI_BIAS_RES><<<dim3(DMODEL / 128, NTOK / 128), 256, GSMEM_BYTES>>>(
        ff, w2, b2, x1, out, NTOK, DMODEL, DFF);
}

// round 10
// speedup vs baseline: 1.2547x; 1.2547x over previous
#include <cuda_runtime.h>
#include <cuda_bf16.h>
#include <stdint.h>
#include <math.h>

// ---------------------------------------------------------------------------
// NeuronBloomBlock: B=2, S=2048, D=2048, H=16, HD=128, FF=8192, fp32.
// R9: R7 tf32 GEMM layout + cp.async 2-stage double buffer.
//     All GEMM inputs pre-rounded to tf32 (weights kernel + producer epilogues)
//     so the mainloop needs no cvt and arithmetic matches R7 exactly.
// ---------------------------------------------------------------------------

#define NTOK   4096
#define DMODEL 2048
#define DQKV   6144
#define DFF    8192
#define SEQ    2048
#define NHEAD  16
#define HEADD  128
#define LNEPS  1e-5f

// scratch layout (floats)
#define OFF_H    ((size_t)0)
#define OFF_QKV  ((size_t)8388608)
#define OFF_ATTN ((size_t)(8388608 + 25165824))
#define OFF_X1   ((size_t)(8388608 + 25165824 + 8388608))
#define OFF_FF   ((size_t)(8388608 + 25165824 + 8388608 + 8388608))
#define OFF_WQKVR (OFF_FF + (size_t)33554432)                 // 2048*6144
#define OFF_WOR   (OFF_WQKVR + (size_t)DMODEL * DQKV)         // 2048*2048
#define OFF_W1R   (OFF_WOR + (size_t)DMODEL * DMODEL)         // 2048*8192
#define OFF_W2R   (OFF_W1R + (size_t)DMODEL * DFF)            // 8192*2048
#define SCRATCH_FLOATS (OFF_W2R + (size_t)DFF * DMODEL)

__device__ float g_scratch[SCRATCH_FLOATS];

__device__ __forceinline__ unsigned int f2tf32(float x) {
    unsigned int y;
    asm("cvt.rna.tf32.f32 %0, %1;" : "=r"(y) : "f"(x));
    return y;
}
__device__ __forceinline__ float rtf(float x) { return __uint_as_float(f2tf32(x)); }

// ---------------------------------------------------------------------------
// Weight rounding: dst = tf32_rna(src), float4 grid-stride.
// ---------------------------------------------------------------------------
__global__ void round_kernel(const float* __restrict__ src, float* __restrict__ dst,
                             int n4) {
    int i = blockIdx.x * blockDim.x + threadIdx.x;
    int stride = gridDim.x * blockDim.x;
    for (; i < n4; i += stride) {
        float4 v = *(const float4*)(src + (size_t)i * 4);
        v.x = rtf(v.x); v.y = rtf(v.y); v.z = rtf(v.z); v.w = rtf(v.w);
        *(float4*)(dst + (size_t)i * 4) = v;
    }
}

// ---------------------------------------------------------------------------
// LayerNorm: one block per row (D=2048), 256 threads; output tf32-rounded.
// ---------------------------------------------------------------------------
__global__ void ln_kernel(const float* __restrict__ x, const float* __restrict__ w,
                          const float* __restrict__ bb, float* __restrict__ out) {
    __shared__ float red[8];
    __shared__ float stat[2];
    int row = blockIdx.x;
    int tid = threadIdx.x;
    const float* xr = x + (size_t)row * DMODEL;

    float4 a = *(const float4*)(xr + tid * 4);
    float4 b = *(const float4*)(xr + 1024 + tid * 4);

    float s = a.x + a.y + a.z + a.w + b.x + b.y + b.z + b.w;
    #pragma unroll
    for (int o = 16; o; o >>= 1) s += __shfl_xor_sync(0xffffffffu, s, o);
    if ((tid & 31) == 0) red[tid >> 5] = s;
    __syncthreads();
    if (tid < 8) {
        float t = red[tid];
        #pragma unroll
        for (int o = 4; o; o >>= 1) t += __shfl_xor_sync(0xffu, t, o);
        if (tid == 0) stat[0] = t;
    }
    __syncthreads();
    float mean = stat[0] * (1.0f / (float)DMODEL);

    float dx0 = a.x - mean, dx1 = a.y - mean, dx2 = a.z - mean, dx3 = a.w - mean;
    float dy0 = b.x - mean, dy1 = b.y - mean, dy2 = b.z - mean, dy3 = b.w - mean;
    float s2 = dx0*dx0 + dx1*dx1 + dx2*dx2 + dx3*dx3
             + dy0*dy0 + dy1*dy1 + dy2*dy2 + dy3*dy3;
    __syncthreads();
    #pragma unroll
    for (int o = 16; o; o >>= 1) s2 += __shfl_xor_sync(0xffffffffu, s2, o);
    if ((tid & 31) == 0) red[tid >> 5] = s2;
    __syncthreads();
    if (tid < 8) {
        float t = red[tid];
        #pragma unroll
        for (int o = 4; o; o >>= 1) t += __shfl_xor_sync(0xffu, t, o);
        if (tid == 0) stat[1] = t;
    }
    __syncthreads();
    float inv = rsqrtf(stat[1] * (1.0f / (float)DMODEL) + LNEPS);

    float4 w0 = *(const float4*)(w + tid * 4);
    float4 w1 = *(const float4*)(w + 1024 + tid * 4);
    float4 g0 = *(const float4*)(bb + tid * 4);
    float4 g1 = *(const float4*)(bb + 1024 + tid * 4);

    float* orow = out + (size_t)row * DMODEL;
    float4 r0, r1;
    r0.x = rtf(dx0 * inv * w0.x + g0.x); r0.y = rtf(dx1 * inv * w0.y + g0.y);
    r0.z = rtf(dx2 * inv * w0.z + g0.z); r0.w = rtf(dx3 * inv * w0.w + g0.w);
    r1.x = rtf(dy0 * inv * w1.x + g1.x); r1.y = rtf(dy1 * inv * w1.y + g1.y);
    r1.z = rtf(dy2 * inv * w1.z + g1.z); r1.w = rtf(dy3 * inv * w1.w + g1.w);
    *(float4*)(orow + tid * 4) = r0;
    *(float4*)(orow + 1024 + tid * 4) = r1;
}

// ---------------------------------------------------------------------------
// TF32 tensor-core GEMM, cp.async double-buffered.
// Block 128x128, K-tile 32, 128 threads = 4 warps (2x2), warp tile 64x64.
// Inputs must already be tf32-rounded fp32.
// ---------------------------------------------------------------------------
#define EPI_BIAS      0
#define EPI_BIAS_RES  1
#define EPI_BIAS_GELU 2

__device__ __forceinline__ float gelu_tanh(float v) {
    float t = tanhf(0.7978845608028654f * (v + 0.044715f * v * v * v));
    return 0.5f * v * (1.0f + t);
}

__device__ __forceinline__ void mma_tf32(float c[4],
        unsigned int a0, unsigned int a1, unsigned int a2, unsigned int a3,
        unsigned int b0, unsigned int b1) {
    asm volatile(
        "mma.sync.aligned.m16n8k8.row.col.f32.tf32.tf32.f32 "
        "{%0,%1,%2,%3}, {%4,%5,%6,%7}, {%8,%9}, {%0,%1,%2,%3};\n"
        : "+f"(c[0]), "+f"(c[1]), "+f"(c[2]), "+f"(c[3])
        : "r"(a0), "r"(a1), "r"(a2), "r"(a3), "r"(b0), "r"(b1));
}

__device__ __forceinline__ void cp16(void* smem, const void* gmem) {
    unsigned int sa = (unsigned int)__cvta_generic_to_shared(smem);
    asm volatile("cp.async.ca.shared.global [%0], [%1], 16;\n"
                 :: "r"(sa), "l"(gmem));
}
__device__ __forceinline__ void cp_commit() {
    asm volatile("cp.async.commit_group;\n");
}
template<int N>
__device__ __forceinline__ void cp_wait() {
    asm volatile("cp.async.wait_group %0;\n" :: "n"(N));
}

// smem layout (floats): A buffers 2 x 128 x 44, then B buffers 2 x 32 x 136.
#define APAD 44
#define BPAD 136
#define ASZ (128 * APAD)
#define BSZ (32 * BPAD)
#define GSMEM_BYTES ((2 * ASZ + 2 * BSZ) * 4)
#define AS(buf, r, k) sm[(buf) * ASZ + (r) * APAD + (k)]
#define BS(buf, r, c) sm[2 * ASZ + (buf) * BSZ + (r) * BPAD + (c)]

template<int EPI>
__global__ __launch_bounds__(128, 2)
void tgemm_kernel(const float* __restrict__ A, const float* __restrict__ W,
                  const float* __restrict__ bias, const float* __restrict__ res,
                  float* __restrict__ C, int M, int N, int K) {
    extern __shared__ float sm[];

    int tid = threadIdx.x;
    int lane = tid & 31;
    int wid  = tid >> 5;
    int warp_m = wid >> 1;          // 0..1
    int warp_n = wid & 1;           // 0..1
    int bm = blockIdx.y * 128;
    int bn = blockIdx.x * 128;

    int lr = lane >> 2;   // 0..7
    int lc = lane & 3;    // 0..3

    float acc[4][8][4];
    #pragma unroll
    for (int mt = 0; mt < 4; ++mt)
        #pragma unroll
        for (int nt = 0; nt < 8; ++nt)
            #pragma unroll
            for (int r = 0; r < 4; ++r) acc[mt][nt][r] = 0.0f;

    // per-thread load coords
    int ar = tid >> 3;                 // A row 0..15 (stride 16 over 8 chunks)
    int ak = (tid & 7) << 2;           // A k4
    int br = tid >> 5;                 // B k-row 0..3 (stride 4)
    int bc = (tid & 31) << 2;          // B col4

    const float* Abase = A + (size_t)bm * K;
    const float* Wbase = W + bn;

    // issue one stage's cp.async group
    auto issue = [&](int stage, int buf) {
        int k0 = stage << 5;
        #pragma unroll
        for (int u = 0; u < 8; ++u) {
            int r = ar + u * 16;
            cp16(&AS(buf, r, ak), Abase + (size_t)r * K + k0 + ak);
            int r2 = br + u * 4;
            cp16(&BS(buf, r2, bc), Wbase + (size_t)(k0 + r2) * N + bc);
        }
        cp_commit();
    };

    int nk = K >> 5;
    issue(0, 0);
    issue(1, 1);

    for (int kt = 0; kt < nk; ++kt) {
        if (kt == nk - 1) cp_wait<0>(); else cp_wait<1>();
        __syncthreads();

        int cur = kt & 1;
        #pragma unroll
        for (int ks = 0; ks < 4; ++ks) {
            unsigned int af[4][4];
            #pragma unroll
            for (int mt = 0; mt < 4; ++mt) {
                int row = warp_m * 64 + mt * 16 + lr;
                int col = ks * 8 + lc;
                af[mt][0] = __float_as_uint(AS(cur, row, col));
                af[mt][1] = __float_as_uint(AS(cur, row + 8, col));
                af[mt][2] = __float_as_uint(AS(cur, row, col + 4));
                af[mt][3] = __float_as_uint(AS(cur, row + 8, col + 4));
            }
            unsigned int bf[8][2];
            #pragma unroll
            for (int nt = 0; nt < 8; ++nt) {
                int ncol = warp_n * 64 + nt * 8 + lr;
                int krow = ks * 8 + lc;
                bf[nt][0] = __float_as_uint(BS(cur, krow, ncol));
                bf[nt][1] = __float_as_uint(BS(cur, krow + 4, ncol));
            }
            #pragma unroll
            for (int mt = 0; mt < 4; ++mt)
                #pragma unroll
                for (int nt = 0; nt < 8; ++nt)
                    mma_tf32(acc[mt][nt], af[mt][0], af[mt][1], af[mt][2], af[mt][3],
                             bf[nt][0], bf[nt][1]);
        }

        if (kt + 2 < nk) {
            __syncthreads();           // all reads of this buffer done
            issue(kt + 2, cur);        // refill the buffer just consumed
        }
    }

    // ---- epilogue ----
    #pragma unroll
    for (int mt = 0; mt < 4; ++mt) {
        int gr0 = bm + warp_m * 64 + mt * 16 + lr;
        int gr1 = gr0 + 8;
        #pragma unroll
        for (int nt = 0; nt < 8; ++nt) {
            int gc = bn + warp_n * 64 + nt * 8 + (lc << 1);
            float2 bv = *(const float2*)(bias + gc);
            float2 v0, v1;
            v0.x = acc[mt][nt][0] + bv.x; v0.y = acc[mt][nt][1] + bv.y;
            v1.x = acc[mt][nt][2] + bv.x; v1.y = acc[mt][nt][3] + bv.y;
            if (EPI == EPI_BIAS_RES) {
                float2 r0 = *(const float2*)(res + (size_t)gr0 * N + gc);
                float2 r1 = *(const float2*)(res + (size_t)gr1 * N + gc);
                v0.x += r0.x; v0.y += r0.y;
                v1.x += r1.x; v1.y += r1.y;
            }
            if (EPI == EPI_BIAS_GELU) {
                // output feeds the W2 GEMM: round to tf32 here
                v0.x = rtf(gelu_tanh(v0.x)); v0.y = rtf(gelu_tanh(v0.y));
                v1.x = rtf(gelu_tanh(v1.x)); v1.y = rtf(gelu_tanh(v1.y));
            }
            *(float2*)(C + (size_t)gr0 * N + gc) = v0;
            *(float2*)(C + (size_t)gr1 * N + gc) = v1;
        }
    }
}

// ---------------------------------------------------------------------------
// Flash attention (fp32) with ALiBi + causal mask; output tf32-rounded
// (it feeds the WO GEMM).
// ---------------------------------------------------------------------------
#define AT_SMEM ((3 * 64 * 132 + 64 * 68) * 4)

__global__ __launch_bounds__(256)
void attn_kernel(const float* __restrict__ qkv, float* __restrict__ out) {
    extern __shared__ float sm[];
    float* Qs = sm;                  // [64][132]
    float* Ks = sm + 64 * 132;       // [64][132]
    float* Vs = sm + 2 * 64 * 132;   // [64][132]
    float* Ps = sm + 3 * 64 * 132;   // [64][68]

    int tid = threadIdx.x;
    int tx = tid & 15, ty = tid >> 4;
    int qt = blockIdx.x, h = blockIdx.y, b = blockIdx.z;
    int q0 = qt * 64;

    const float scale = 0.08838834764831845f;   // 1/sqrt(128)
    float slope = exp2f(-0.5f * (float)(h + 1));

    const float* qbase = qkv + (size_t)b * SEQ * DQKV + (size_t)h * HEADD;
    const float* kbase = qbase + DMODEL;
    const float* vbase = qbase + 2 * DMODEL;

    for (int i = tid; i < 64 * 32; i += 256) {
        int r = i >> 5, c4 = (i & 31) << 2;
        float4 v = *(const float4*)(qbase + (size_t)(q0 + r) * DQKV + c4);
        Qs[r * 132 + c4 + 0] = v.x * scale;
        Qs[r * 132 + c4 + 1] = v.y * scale;
        Qs[r * 132 + c4 + 2] = v.z * scale;
        Qs[r * 132 + c4 + 3] = v.w * scale;
    }

    float m_i[4], l_i[4], acc[4][8];
    #pragma unroll
    for (int i = 0; i < 4; ++i) {
        m_i[i] = -INFINITY; l_i[i] = 0.0f;
        #pragma unroll
        for (int c = 0; c < 8; ++c) acc[i][c] = 0.0f;
    }

    int nkb = qt + 1;
    for (int kb = 0; kb < nkb; ++kb) {
        __syncthreads();
        for (int i = tid; i < 64 * 32; i += 256) {
            int r = i >> 5, c4 = (i & 31) << 2;
            *(float4*)&Ks[r * 132 + c4] =
                *(const float4*)(kbase + (size_t)(kb * 64 + r) * DQKV + c4);
            *(float4*)&Vs[r * 132 + c4] =
                *(const float4*)(vbase + (size_t)(kb * 64 + r) * DQKV + c4);
        }
        __syncthreads();

        float s[4][4];
        #pragma unroll
        for (int i = 0; i < 4; ++i)
            #pragma unroll
            for (int j = 0; j < 4; ++j) s[i][j] = 0.0f;

        for (int d4 = 0; d4 < 32; ++d4) {
            float4 qv[4], kv[4];
            #pragma unroll
            for (int i = 0; i < 4; ++i)
                qv[i] = *(const float4*)&Qs[(ty * 4 + i) * 132 + d4 * 4];
            #pragma unroll
            for (int j = 0; j < 4; ++j)
                kv[j] = *(const float4*)&Ks[(j * 16 + tx) * 132 + d4 * 4];
            #pragma unroll
            for (int i = 0; i < 4; ++i)
                #pragma unroll
                for (int j = 0; j < 4; ++j) {
                    s[i][j] = fmaf(qv[i].x, kv[j].x, s[i][j]);
                    s[i][j] = fmaf(qv[i].y, kv[j].y, s[i][j]);
                    s[i][j] = fmaf(qv[i].z, kv[j].z, s[i][j]);
                    s[i][j] = fmaf(qv[i].w, kv[j].w, s[i][j]);
                }
        }

        bool diag = (kb == qt);
        float a4[4];
        #pragma unroll
        for (int i = 0; i < 4; ++i) {
            int gr = q0 + ty * 4 + i;
            float rowmax = -1e30f;
            #pragma unroll
            for (int j = 0; j < 4; ++j) {
                int gc = kb * 64 + j * 16 + tx;
                float val = s[i][j] + slope * (float)(gc - gr);
                if (diag && gc > gr) val = -1e30f;
                s[i][j] = val;
                rowmax = fmaxf(rowmax, val);
            }
            #pragma unroll
            for (int o = 8; o; o >>= 1)
                rowmax = fmaxf(rowmax, __shfl_xor_sync(0xffffffffu, rowmax, o, 16));
            float mnew = fmaxf(m_i[i], rowmax);
            float alpha = expf(m_i[i] - mnew);
            float rowsum = 0.0f;
            #pragma unroll
            for (int j = 0; j < 4; ++j) {
                float p = expf(s[i][j] - mnew);
                s[i][j] = p;
                rowsum += p;
            }
            #pragma unroll
            for (int o = 8; o; o >>= 1)
                rowsum += __shfl_xor_sync(0xffffffffu, rowsum, o, 16);
            l_i[i] = l_i[i] * alpha + rowsum;
            m_i[i] = mnew;
            a4[i] = alpha;
        }

        #pragma unroll
        for (int i = 0; i < 4; ++i)
            #pragma unroll
            for (int j = 0; j < 4; ++j)
                Ps[(ty * 4 + i) * 68 + j * 16 + tx] = s[i][j];
        __syncthreads();

        #pragma unroll
        for (int i = 0; i < 4; ++i)
            #pragma unroll
            for (int c = 0; c < 8; ++c) acc[i][c] *= a4[i];

        #pragma unroll 4
        for (int k = 0; k < 64; ++k) {
            float4 v0 = *(const float4*)&Vs[k * 132 + tx * 4];
            float4 v1 = *(const float4*)&Vs[k * 132 + 64 + tx * 4];
            #pragma unroll
            for (int i = 0; i < 4; ++i) {
                float p = Ps[(ty * 4 + i) * 68 + k];
                acc[i][0] = fmaf(p, v0.x, acc[i][0]);
                acc[i][1] = fmaf(p, v0.y, acc[i][1]);
                acc[i][2] = fmaf(p, v0.z, acc[i][2]);
                acc[i][3] = fmaf(p, v0.w, acc[i][3]);
                acc[i][4] = fmaf(p, v1.x, acc[i][4]);
                acc[i][5] = fmaf(p, v1.y, acc[i][5]);
                acc[i][6] = fmaf(p, v1.z, acc[i][6]);
                acc[i][7] = fmaf(p, v1.w, acc[i][7]);
            }
        }
    }

    #pragma unroll
    for (int i = 0; i < 4; ++i) {
        float inv = 1.0f / l_i[i];
        size_t orow = ((size_t)(b * SEQ + q0 + ty * 4 + i)) * DMODEL + h * HEADD;
        float4 o0, o1;
        o0.x = rtf(acc[i][0] * inv); o0.y = rtf(acc[i][1] * inv);
        o0.z = rtf(acc[i][2] * inv); o0.w = rtf(acc[i][3] * inv);
        o1.x = rtf(acc[i][4] * inv); o1.y = rtf(acc[i][5] * inv);
        o1.z = rtf(acc[i][6] * inv); o1.w = rtf(acc[i][7] * inv);
        *(float4*)(out + orow + tx * 4) = o0;
        *(float4*)(out + orow + 64 + tx * 4) = o1;
    }
}

// ---------------------------------------------------------------------------
extern "C" void kernel_launch(void* const* d_in, const int* in_sizes, int n_in,
                              void* d_out, int out_size) {
    const float* x     = (const float*)d_in[0];
    const float* ln1_w = (const float*)d_in[1];
    const float* ln1_b = (const float*)d_in[2];
    const float* wqkv  = (const float*)d_in[3];
    const float* bqkv  = (const float*)d_in[4];
    const float* wo    = (const float*)d_in[5];
    const float* bo    = (const float*)d_in[6];
    const float* ln2_w = (const float*)d_in[7];
    const float* ln2_b = (const float*)d_in[8];
    const float* w1    = (const float*)d_in[9];
    const float* b1    = (const float*)d_in[10];
    const float* w2    = (const float*)d_in[11];
    const float* b2    = (const float*)d_in[12];
    float* out = (float*)d_out;

    float* base = nullptr;
    cudaGetSymbolAddress((void**)&base, g_scratch);
    float* h     = base + OFF_H;
    float* qkv   = base + OFF_QKV;
    float* attn  = base + OFF_ATTN;
    float* x1    = base + OFF_X1;
    float* ff    = base + OFF_FF;
    float* wqkvr = base + OFF_WQKVR;
    float* wor   = base + OFF_WOR;
    float* w1r   = base + OFF_W1R;
    float* w2r   = base + OFF_W2R;

    cudaFuncSetAttribute(attn_kernel, cudaFuncAttributeMaxDynamicSharedMemorySize, AT_SMEM);
    cudaFuncSetAttribute(tgemm_kernel<EPI_BIAS>,
                         cudaFuncAttributeMaxDynamicSharedMemorySize, GSMEM_BYTES);
    cudaFuncSetAttribute(tgemm_kernel<EPI_BIAS_RES>,
                         cudaFuncAttributeMaxDynamicSharedMemorySize, GSMEM_BYTES);
    cudaFuncSetAttribute(tgemm_kernel<EPI_BIAS_GELU>,
                         cudaFuncAttributeMaxDynamicSharedMemorySize, GSMEM_BYTES);

    // 0. round weights to tf32 (inputs to tensor cores)
    round_kernel<<<2048, 256>>>(wqkv, wqkvr, (DMODEL * DQKV) / 4);
    round_kernel<<<1024, 256>>>(wo,   wor,   (DMODEL * DMODEL) / 4);
    round_kernel<<<2048, 256>>>(w1,   w1r,   (DMODEL * DFF) / 4);
    round_kernel<<<2048, 256>>>(w2,   w2r,   (DFF * DMODEL) / 4);

    // 1. h = LN1(x)  (tf32-rounded output)
    ln_kernel<<<NTOK, 256>>>(x, ln1_w, ln1_b, h);
    // 2. qkv = h @ wqkv + bqkv
    tgemm_kernel<EPI_BIAS><<<dim3(DQKV / 128, NTOK / 128), 128, GSMEM_BYTES>>>(
        h, wqkvr, bqkv, nullptr, qkv, NTOK, DQKV, DMODEL);
    // 3. attention (tf32-rounded output)
    attn_kernel<<<dim3(SEQ / 64, NHEAD, 2), 256, AT_SMEM>>>(qkv, attn);
    // 4. x1 = x + attn @ wo + bo
    tgemm_kernel<EPI_BIAS_RES><<<dim3(DMODEL / 128, NTOK / 128), 128, GSMEM_BYTES>>>(
        attn, wor, bo, x, x1, NTOK, DMODEL, DMODEL);
    // 5. h = LN2(x1)  (tf32-rounded output)
    ln_kernel<<<NTOK, 256>>>(x1, ln2_w, ln2_b, h);
    // 6. ff = gelu(h @ w1 + b1)  (tf32-rounded output)
    tgemm_kernel<EPI_BIAS_GELU><<<dim3(DFF / 128, NTOK / 128), 128, GSMEM_BYTES>>>(
        h, w1r, b1, nullptr, ff, NTOK, DFF, DMODEL);
    // 7. out = x1 + ff @ w2 + b2
    tgemm_kernel<EPI_BIAS_RES><<<dim3(DMODEL / 128, NTOK / 128), 128, GSMEM_BYTES>>>(
        ff, w2r, b2, x1, out, NTOK, DMODEL, DFF);
}

// round 11
// speedup vs baseline: 1.5672x; 1.2491x over previous
#include <cuda_runtime.h>
#include <cuda_bf16.h>
#include <stdint.h>
#include <math.h>

// ---------------------------------------------------------------------------
// NeuronBloomBlock: B=2, S=2048, D=2048, H=16, HD=128, FF=8192, fp32.
// R11: R9 GEMMs (cp.async tf32 mma) + tensor-core flash attention (tf32 mma,
//      Q-tile 128, masked-block skip) + FMA-pipe polynomial exp/tanh.
// ---------------------------------------------------------------------------

#define NTOK   4096
#define DMODEL 2048
#define DQKV   6144
#define DFF    8192
#define SEQ    2048
#define NHEAD  16
#define HEADD  128
#define LNEPS  1e-5f

// scratch layout (floats)
#define OFF_H    ((size_t)0)
#define OFF_QKV  ((size_t)8388608)
#define OFF_ATTN ((size_t)(8388608 + 25165824))
#define OFF_X1   ((size_t)(8388608 + 25165824 + 8388608))
#define OFF_FF   ((size_t)(8388608 + 25165824 + 8388608 + 8388608))
#define OFF_WQKVR (OFF_FF + (size_t)33554432)
#define OFF_WOR   (OFF_WQKVR + (size_t)DMODEL * DQKV)
#define OFF_W1R   (OFF_WOR + (size_t)DMODEL * DMODEL)
#define OFF_W2R   (OFF_W1R + (size_t)DMODEL * DFF)
#define SCRATCH_FLOATS (OFF_W2R + (size_t)DFF * DMODEL)

__device__ float g_scratch[SCRATCH_FLOATS];

__device__ __forceinline__ unsigned int f2tf32(float x) {
    unsigned int y;
    asm("cvt.rna.tf32.f32 %0, %1;" : "=r"(y) : "f"(x));
    return y;
}
__device__ __forceinline__ float rtf(float x) { return __uint_as_float(f2tf32(x)); }

// exp(x) for x <= 0 via 2^t, FMA-pipe only (deg-5 poly, rel err ~2e-6).
__device__ __forceinline__ float fast_exp(float x) {
    float t = x * 1.4426950408889634f;
    t = fmaxf(t, -126.0f);
    float r = t + 12582912.0f;           // round-to-nearest-int magic
    float i = r - 12582912.0f;
    float f = t - i;                     // [-0.5, 0.5]
    float p = 0.00133335581f;
    p = fmaf(p, f, 0.00961812910f);
    p = fmaf(p, f, 0.0555041087f);
    p = fmaf(p, f, 0.240226507f);
    p = fmaf(p, f, 0.693147180f);
    p = fmaf(p, f, 1.0f);
    float s = __int_as_float(((int)i + 127) << 23);
    return p * s;
}

// tanh-approx GELU via fast 2^t (arg bounded, saturating clamp).
__device__ __forceinline__ float gelu_fast(float v) {
    float z = fmaf(0.044715f * v, v * v, v) * 0.7978845608028654f;
    float t = z * 2.8853900817779268f;   // 2z*log2(e)
    t = fminf(fmaxf(t, -30.0f), 30.0f);
    float r = t + 12582912.0f;
    float i = r - 12582912.0f;
    float f = t - i;
    float p = 0.00133335581f;
    p = fmaf(p, f, 0.00961812910f);
    p = fmaf(p, f, 0.0555041087f);
    p = fmaf(p, f, 0.240226507f);
    p = fmaf(p, f, 0.693147180f);
    p = fmaf(p, f, 1.0f);
    float e2z = p * __int_as_float(((int)i + 127) << 23);
    float th = 1.0f - __fdividef(2.0f, e2z + 1.0f);
    return 0.5f * v * (1.0f + th);
}

// ---------------------------------------------------------------------------
// Weight rounding: dst = tf32_rna(src), float4 grid-stride.
// ---------------------------------------------------------------------------
__global__ void round_kernel(const float* __restrict__ src, float* __restrict__ dst,
                             int n4) {
    int i = blockIdx.x * blockDim.x + threadIdx.x;
    int stride = gridDim.x * blockDim.x;
    for (; i < n4; i += stride) {
        float4 v = *(const float4*)(src + (size_t)i * 4);
        v.x = rtf(v.x); v.y = rtf(v.y); v.z = rtf(v.z); v.w = rtf(v.w);
        *(float4*)(dst + (size_t)i * 4) = v;
    }
}

// ---------------------------------------------------------------------------
// LayerNorm: one block per row (D=2048), 256 threads; output tf32-rounded.
// ---------------------------------------------------------------------------
__global__ void ln_kernel(const float* __restrict__ x, const float* __restrict__ w,
                          const float* __restrict__ bb, float* __restrict__ out) {
    __shared__ float red[8];
    __shared__ float stat[2];
    int row = blockIdx.x;
    int tid = threadIdx.x;
    const float* xr = x + (size_t)row * DMODEL;

    float4 a = *(const float4*)(xr + tid * 4);
    float4 b = *(const float4*)(xr + 1024 + tid * 4);

    float s = a.x + a.y + a.z + a.w + b.x + b.y + b.z + b.w;
    #pragma unroll
    for (int o = 16; o; o >>= 1) s += __shfl_xor_sync(0xffffffffu, s, o);
    if ((tid & 31) == 0) red[tid >> 5] = s;
    __syncthreads();
    if (tid < 8) {
        float t = red[tid];
        #pragma unroll
        for (int o = 4; o; o >>= 1) t += __shfl_xor_sync(0xffu, t, o);
        if (tid == 0) stat[0] = t;
    }
    __syncthreads();
    float mean = stat[0] * (1.0f / (float)DMODEL);

    float dx0 = a.x - mean, dx1 = a.y - mean, dx2 = a.z - mean, dx3 = a.w - mean;
    float dy0 = b.x - mean, dy1 = b.y - mean, dy2 = b.z - mean, dy3 = b.w - mean;
    float s2 = dx0*dx0 + dx1*dx1 + dx2*dx2 + dx3*dx3
             + dy0*dy0 + dy1*dy1 + dy2*dy2 + dy3*dy3;
    __syncthreads();
    #pragma unroll
    for (int o = 16; o; o >>= 1) s2 += __shfl_xor_sync(0xffffffffu, s2, o);
    if ((tid & 31) == 0) red[tid >> 5] = s2;
    __syncthreads();
    if (tid < 8) {
        float t = red[tid];
        #pragma unroll
        for (int o = 4; o; o >>= 1) t += __shfl_xor_sync(0xffu, t, o);
        if (tid == 0) stat[1] = t;
    }
    __syncthreads();
    float inv = rsqrtf(stat[1] * (1.0f / (float)DMODEL) + LNEPS);

    float4 w0 = *(const float4*)(w + tid * 4);
    float4 w1 = *(const float4*)(w + 1024 + tid * 4);
    float4 g0 = *(const float4*)(bb + tid * 4);
    float4 g1 = *(const float4*)(bb + 1024 + tid * 4);

    float* orow = out + (size_t)row * DMODEL;
    float4 r0, r1;
    r0.x = rtf(dx0 * inv * w0.x + g0.x); r0.y = rtf(dx1 * inv * w0.y + g0.y);
    r0.z = rtf(dx2 * inv * w0.z + g0.z); r0.w = rtf(dx3 * inv * w0.w + g0.w);
    r1.x = rtf(dy0 * inv * w1.x + g1.x); r1.y = rtf(dy1 * inv * w1.y + g1.y);
    r1.z = rtf(dy2 * inv * w1.z + g1.z); r1.w = rtf(dy3 * inv * w1.w + g1.w);
    *(float4*)(orow + tid * 4) = r0;
    *(float4*)(orow + 1024 + tid * 4) = r1;
}

// ---------------------------------------------------------------------------
// TF32 tensor-core GEMM, cp.async double-buffered (R9, unchanged except gelu).
// ---------------------------------------------------------------------------
#define EPI_BIAS      0
#define EPI_BIAS_RES  1
#define EPI_BIAS_GELU 2

__device__ __forceinline__ void mma_tf32(float c[4],
        unsigned int a0, unsigned int a1, unsigned int a2, unsigned int a3,
        unsigned int b0, unsigned int b1) {
    asm volatile(
        "mma.sync.aligned.m16n8k8.row.col.f32.tf32.tf32.f32 "
        "{%0,%1,%2,%3}, {%4,%5,%6,%7}, {%8,%9}, {%0,%1,%2,%3};\n"
        : "+f"(c[0]), "+f"(c[1]), "+f"(c[2]), "+f"(c[3])
        : "r"(a0), "r"(a1), "r"(a2), "r"(a3), "r"(b0), "r"(b1));
}

__device__ __forceinline__ void cp16(void* smem, const void* gmem) {
    unsigned int sa = (unsigned int)__cvta_generic_to_shared(smem);
    asm volatile("cp.async.ca.shared.global [%0], [%1], 16;\n"
                 :: "r"(sa), "l"(gmem));
}
__device__ __forceinline__ void cp_commit() {
    asm volatile("cp.async.commit_group;\n");
}
template<int N>
__device__ __forceinline__ void cp_wait() {
    asm volatile("cp.async.wait_group %0;\n" :: "n"(N));
}

#define APAD 44
#define BPAD 136
#define ASZ (128 * APAD)
#define BSZ (32 * BPAD)
#define GSMEM_BYTES ((2 * ASZ + 2 * BSZ) * 4)
#define AS(buf, r, k) sm[(buf) * ASZ + (r) * APAD + (k)]
#define BS(buf, r, c) sm[2 * ASZ + (buf) * BSZ + (r) * BPAD + (c)]

template<int EPI>
__global__ __launch_bounds__(128, 2)
void tgemm_kernel(const float* __restrict__ A, const float* __restrict__ W,
                  const float* __restrict__ bias, const float* __restrict__ res,
                  float* __restrict__ C, int M, int N, int K) {
    extern __shared__ float sm[];

    int tid = threadIdx.x;
    int lane = tid & 31;
    int wid  = tid >> 5;
    int warp_m = wid >> 1;
    int warp_n = wid & 1;
    int bm = blockIdx.y * 128;
    int bn = blockIdx.x * 128;

    int lr = lane >> 2;
    int lc = lane & 3;

    float acc[4][8][4];
    #pragma unroll
    for (int mt = 0; mt < 4; ++mt)
        #pragma unroll
        for (int nt = 0; nt < 8; ++nt)
            #pragma unroll
            for (int r = 0; r < 4; ++r) acc[mt][nt][r] = 0.0f;

    int ar = tid >> 3;
    int ak = (tid & 7) << 2;
    int br = tid >> 5;
    int bc = (tid & 31) << 2;

    const float* Abase = A + (size_t)bm * K;
    const float* Wbase = W + bn;

    auto issue = [&](int stage, int buf) {
        int k0 = stage << 5;
        #pragma unroll
        for (int u = 0; u < 8; ++u) {
            int r = ar + u * 16;
            cp16(&AS(buf, r, ak), Abase + (size_t)r * K + k0 + ak);
            int r2 = br + u * 4;
            cp16(&BS(buf, r2, bc), Wbase + (size_t)(k0 + r2) * N + bc);
        }
        cp_commit();
    };

    int nk = K >> 5;
    issue(0, 0);
    issue(1, 1);

    for (int kt = 0; kt < nk; ++kt) {
        if (kt == nk - 1) cp_wait<0>(); else cp_wait<1>();
        __syncthreads();

        int cur = kt & 1;
        #pragma unroll
        for (int ks = 0; ks < 4; ++ks) {
            unsigned int af[4][4];
            #pragma unroll
            for (int mt = 0; mt < 4; ++mt) {
                int row = warp_m * 64 + mt * 16 + lr;
                int col = ks * 8 + lc;
                af[mt][0] = __float_as_uint(AS(cur, row, col));
                af[mt][1] = __float_as_uint(AS(cur, row + 8, col));
                af[mt][2] = __float_as_uint(AS(cur, row, col + 4));
                af[mt][3] = __float_as_uint(AS(cur, row + 8, col + 4));
            }
            unsigned int bf[8][2];
            #pragma unroll
            for (int nt = 0; nt < 8; ++nt) {
                int ncol = warp_n * 64 + nt * 8 + lr;
                int krow = ks * 8 + lc;
                bf[nt][0] = __float_as_uint(BS(cur, krow, ncol));
                bf[nt][1] = __float_as_uint(BS(cur, krow + 4, ncol));
            }
            #pragma unroll
            for (int mt = 0; mt < 4; ++mt)
                #pragma unroll
                for (int nt = 0; nt < 8; ++nt)
                    mma_tf32(acc[mt][nt], af[mt][0], af[mt][1], af[mt][2], af[mt][3],
                             bf[nt][0], bf[nt][1]);
        }

        if (kt + 2 < nk) {
            __syncthreads();
            issue(kt + 2, cur);
        }
    }

    #pragma unroll
    for (int mt = 0; mt < 4; ++mt) {
        int gr0 = bm + warp_m * 64 + mt * 16 + lr;
        int gr1 = gr0 + 8;
        #pragma unroll
        for (int nt = 0; nt < 8; ++nt) {
            int gc = bn + warp_n * 64 + nt * 8 + (lc << 1);
            float2 bv = *(const float2*)(bias + gc);
            float2 v0, v1;
            v0.x = acc[mt][nt][0] + bv.x; v0.y = acc[mt][nt][1] + bv.y;
            v1.x = acc[mt][nt][2] + bv.x; v1.y = acc[mt][nt][3] + bv.y;
            if (EPI == EPI_BIAS_RES) {
                float2 r0 = *(const float2*)(res + (size_t)gr0 * N + gc);
                float2 r1 = *(const float2*)(res + (size_t)gr1 * N + gc);
                v0.x += r0.x; v0.y += r0.y;
                v1.x += r1.x; v1.y += r1.y;
            }
            if (EPI == EPI_BIAS_GELU) {
                v0.x = rtf(gelu_fast(v0.x)); v0.y = rtf(gelu_fast(v0.y));
                v1.x = rtf(gelu_fast(v1.x)); v1.y = rtf(gelu_fast(v1.y));
            }
            *(float2*)(C + (size_t)gr0 * N + gc) = v0;
            *(float2*)(C + (size_t)gr1 * N + gc) = v1;
        }
    }
}

// ---------------------------------------------------------------------------
// Tensor-core flash attention (tf32 mma) with ALiBi + causal mask.
// Q tile 128 rows, 8 warps (16 rows each), K-block 64, HD=128.
// Output tf32-rounded (feeds WO GEMM).
// ---------------------------------------------------------------------------
#define ATQ 128
#define QP  132
#define KP  132
#define VP  136
#define PP  68
#define AT2_SMEM ((ATQ*QP + 64*KP + 64*VP + ATQ*PP) * 4)

__global__ __launch_bounds__(256)
void attn_kernel(const float* __restrict__ qkv, float* __restrict__ out) {
    extern __shared__ float sm[];
    float* Qs = sm;
    float* Ks = Qs + ATQ * QP;
    float* Vs = Ks + 64 * KP;
    float* Ps = Vs + 64 * VP;

    int tid = threadIdx.x;
    int lane = tid & 31, w = tid >> 5;
    int lr = lane >> 2, lc = lane & 3;
    int qt = gridDim.x - 1 - blockIdx.x;    // long CTAs first
    int h = blockIdx.y, b = blockIdx.z;
    int q0 = qt * ATQ;

    const float scale = 0.08838834764831845f;   // 1/sqrt(128)
    float slope = exp2f(-0.5f * (float)(h + 1));

    const float* qbase = qkv + (size_t)b * SEQ * DQKV + (size_t)h * HEADD;
    const float* kbase = qbase + DMODEL;
    const float* vbase = qbase + 2 * DMODEL;

    // load Q tile (scaled + tf32-rounded)
    for (int i = tid; i < ATQ * 32; i += 256) {
        int r = i >> 5, c4 = (i & 31) << 2;
        float4 v = *(const float4*)(qbase + (size_t)(q0 + r) * DQKV + c4);
        Qs[r * QP + c4 + 0] = rtf(v.x * scale);
        Qs[r * QP + c4 + 1] = rtf(v.y * scale);
        Qs[r * QP + c4 + 2] = rtf(v.z * scale);
        Qs[r * QP + c4 + 3] = rtf(v.w * scale);
    }

    int row0 = q0 + w * 16 + lr;
    int row1 = row0 + 8;
    int wmax = q0 + w * 16 + 15;

    float m0 = -INFINITY, m1 = -INFINITY, l0 = 0.0f, l1 = 0.0f;
    float o[16][4];
    #pragma unroll
    for (int nt = 0; nt < 16; ++nt)
        #pragma unroll
        for (int r = 0; r < 4; ++r) o[nt][r] = 0.0f;

    int nkb = 2 * qt + 2;
    for (int kb = 0; kb < nkb; ++kb) {
        int k0 = kb * 64;
        __syncthreads();
        for (int i = tid; i < 64 * 32; i += 256) {
            int r = i >> 5, c4 = (i & 31) << 2;
            float4 kv = *(const float4*)(kbase + (size_t)(k0 + r) * DQKV + c4);
            Ks[r * KP + c4 + 0] = rtf(kv.x);
            Ks[r * KP + c4 + 1] = rtf(kv.y);
            Ks[r * KP + c4 + 2] = rtf(kv.z);
            Ks[r * KP + c4 + 3] = rtf(kv.w);
            float4 vv = *(const float4*)(vbase + (size_t)(k0 + r) * DQKV + c4);
            Vs[r * VP + c4 + 0] = rtf(vv.x);
            Vs[r * VP + c4 + 1] = rtf(vv.y);
            Vs[r * VP + c4 + 2] = rtf(vv.z);
            Vs[r * VP + c4 + 3] = rtf(vv.w);
        }
        __syncthreads();
        if (k0 > wmax) continue;    // fully masked for this warp's rows

        // ---- S = Q @ K^T (16x64 per warp) ----
        float sc[8][4];
        #pragma unroll
        for (int nt = 0; nt < 8; ++nt)
            #pragma unroll
            for (int r = 0; r < 4; ++r) sc[nt][r] = 0.0f;

        #pragma unroll
        for (int ks = 0; ks < 16; ++ks) {
            int qrow = (w * 16 + lr) * QP;
            int col = ks * 8 + lc;
            unsigned int a0 = __float_as_uint(Qs[qrow + col]);
            unsigned int a1 = __float_as_uint(Qs[qrow + 8 * QP + col]);
            unsigned int a2 = __float_as_uint(Qs[qrow + col + 4]);
            unsigned int a3 = __float_as_uint(Qs[qrow + 8 * QP + col + 4]);
            #pragma unroll
            for (int nt = 0; nt < 8; ++nt) {
                unsigned int b0 = __float_as_uint(Ks[(nt * 8 + lr) * KP + col]);
                unsigned int b1 = __float_as_uint(Ks[(nt * 8 + lr) * KP + col + 4]);
                mma_tf32(sc[nt], a0, a1, a2, a3, b0, b1);
            }
        }

        // ---- ALiBi + causal + online softmax ----
        float rmax0 = -1e30f, rmax1 = -1e30f;
        #pragma unroll
        for (int nt = 0; nt < 8; ++nt) {
            int gc = k0 + nt * 8 + 2 * lc;
            float al0 = slope * (float)(gc - row0);
            float v0 = sc[nt][0] + al0;
            float v1 = sc[nt][1] + al0 + slope;
            if (gc > row0)     v0 = -1e30f;
            if (gc + 1 > row0) v1 = -1e30f;
            float al1 = slope * (float)(gc - row1);
            float u0 = sc[nt][2] + al1;
            float u1 = sc[nt][3] + al1 + slope;
            if (gc > row1)     u0 = -1e30f;
            if (gc + 1 > row1) u1 = -1e30f;
            sc[nt][0] = v0; sc[nt][1] = v1; sc[nt][2] = u0; sc[nt][3] = u1;
            rmax0 = fmaxf(rmax0, fmaxf(v0, v1));
            rmax1 = fmaxf(rmax1, fmaxf(u0, u1));
        }
        rmax0 = fmaxf(rmax0, __shfl_xor_sync(0xffffffffu, rmax0, 1));
        rmax0 = fmaxf(rmax0, __shfl_xor_sync(0xffffffffu, rmax0, 2));
        rmax1 = fmaxf(rmax1, __shfl_xor_sync(0xffffffffu, rmax1, 1));
        rmax1 = fmaxf(rmax1, __shfl_xor_sync(0xffffffffu, rmax1, 2));

        float mn0 = fmaxf(m0, rmax0), mn1 = fmaxf(m1, rmax1);
        float alpha0 = fast_exp(m0 - mn0), alpha1 = fast_exp(m1 - mn1);
        m0 = mn0; m1 = mn1;

        __syncwarp();   // all lanes done reading Ps from prev iter before rewrite
        float rs0 = 0.0f, rs1 = 0.0f;
        #pragma unroll
        for (int nt = 0; nt < 8; ++nt) {
            float p0 = fast_exp(sc[nt][0] - mn0);
            float p1 = fast_exp(sc[nt][1] - mn0);
            float p2 = fast_exp(sc[nt][2] - mn1);
            float p3 = fast_exp(sc[nt][3] - mn1);
            rs0 += p0 + p1; rs1 += p2 + p3;
            float2 q01; q01.x = rtf(p0); q01.y = rtf(p1);
            float2 q23; q23.x = rtf(p2); q23.y = rtf(p3);
            *(float2*)&Ps[(w * 16 + lr) * PP + nt * 8 + 2 * lc] = q01;
            *(float2*)&Ps[(w * 16 + lr + 8) * PP + nt * 8 + 2 * lc] = q23;
        }
        rs0 += __shfl_xor_sync(0xffffffffu, rs0, 1);
        rs0 += __shfl_xor_sync(0xffffffffu, rs0, 2);
        rs1 += __shfl_xor_sync(0xffffffffu, rs1, 1);
        rs1 += __shfl_xor_sync(0xffffffffu, rs1, 2);
        l0 = l0 * alpha0 + rs0;
        l1 = l1 * alpha1 + rs1;

        #pragma unroll
        for (int nt = 0; nt < 16; ++nt) {
            o[nt][0] *= alpha0; o[nt][1] *= alpha0;
            o[nt][2] *= alpha1; o[nt][3] *= alpha1;
        }
        __syncwarp();   // Ps writes visible warp-wide

        // ---- O += P @ V (16x128 per warp) ----
        #pragma unroll
        for (int ks = 0; ks < 8; ++ks) {
            int prow = (w * 16 + lr) * PP;
            int col = ks * 8 + lc;
            unsigned int a0 = __float_as_uint(Ps[prow + col]);
            unsigned int a1 = __float_as_uint(Ps[prow + 8 * PP + col]);
            unsigned int a2 = __float_as_uint(Ps[prow + col + 4]);
            unsigned int a3 = __float_as_uint(Ps[prow + 8 * PP + col + 4]);
            #pragma unroll
            for (int nt = 0; nt < 16; ++nt) {
                unsigned int b0 = __float_as_uint(Vs[(col) * VP + nt * 8 + lr]);
                unsigned int b1 = __float_as_uint(Vs[(col + 4) * VP + nt * 8 + lr]);
                mma_tf32(o[nt], a0, a1, a2, a3, b0, b1);
            }
        }
    }

    // ---- epilogue ----
    float inv0 = 1.0f / l0, inv1 = 1.0f / l1;
    size_t or0 = ((size_t)(b * SEQ) + row0) * DMODEL + h * HEADD;
    size_t or1 = or0 + (size_t)8 * DMODEL;
    #pragma unroll
    for (int nt = 0; nt < 16; ++nt) {
        int c = nt * 8 + 2 * lc;
        float2 w0; w0.x = rtf(o[nt][0] * inv0); w0.y = rtf(o[nt][1] * inv0);
        float2 w1; w1.x = rtf(o[nt][2] * inv1); w1.y = rtf(o[nt][3] * inv1);
        *(float2*)(out + or0 + c) = w0;
        *(float2*)(out + or1 + c) = w1;
    }
}

// ---------------------------------------------------------------------------
extern "C" void kernel_launch(void* const* d_in, const int* in_sizes, int n_in,
                              void* d_out, int out_size) {
    const float* x     = (const float*)d_in[0];
    const float* ln1_w = (const float*)d_in[1];
    const float* ln1_b = (const float*)d_in[2];
    const float* wqkv  = (const float*)d_in[3];
    const float* bqkv  = (const float*)d_in[4];
    const float* wo    = (const float*)d_in[5];
    const float* bo    = (const float*)d_in[6];
    const float* ln2_w = (const float*)d_in[7];
    const float* ln2_b = (const float*)d_in[8];
    const float* w1    = (const float*)d_in[9];
    const float* b1    = (const float*)d_in[10];
    const float* w2    = (const float*)d_in[11];
    const float* b2    = (const float*)d_in[12];
    float* out = (float*)d_out;

    float* base = nullptr;
    cudaGetSymbolAddress((void**)&base, g_scratch);
    float* h     = base + OFF_H;
    float* qkv   = base + OFF_QKV;
    float* attn  = base + OFF_ATTN;
    float* x1    = base + OFF_X1;
    float* ff    = base + OFF_FF;
    float* wqkvr = base + OFF_WQKVR;
    float* wor   = base + OFF_WOR;
    float* w1r   = base + OFF_W1R;
    float* w2r   = base + OFF_W2R;

    cudaFuncSetAttribute(attn_kernel, cudaFuncAttributeMaxDynamicSharedMemorySize, AT2_SMEM);
    cudaFuncSetAttribute(tgemm_kernel<EPI_BIAS>,
                         cudaFuncAttributeMaxDynamicSharedMemorySize, GSMEM_BYTES);
    cudaFuncSetAttribute(tgemm_kernel<EPI_BIAS_RES>,
                         cudaFuncAttributeMaxDynamicSharedMemorySize, GSMEM_BYTES);
    cudaFuncSetAttribute(tgemm_kernel<EPI_BIAS_GELU>,
                         cudaFuncAttributeMaxDynamicSharedMemorySize, GSMEM_BYTES);

    // 0. round weights to tf32
    round_kernel<<<2048, 256>>>(wqkv, wqkvr, (DMODEL * DQKV) / 4);
    round_kernel<<<1024, 256>>>(wo,   wor,   (DMODEL * DMODEL) / 4);
    round_kernel<<<2048, 256>>>(w1,   w1r,   (DMODEL * DFF) / 4);
    round_kernel<<<2048, 256>>>(w2,   w2r,   (DFF * DMODEL) / 4);

    // 1. h = LN1(x)
    ln_kernel<<<NTOK, 256>>>(x, ln1_w, ln1_b, h);
    // 2. qkv = h @ wqkv + bqkv
    tgemm_kernel<EPI_BIAS><<<dim3(DQKV / 128, NTOK / 128), 128, GSMEM_BYTES>>>(
        h, wqkvr, bqkv, nullptr, qkv, NTOK, DQKV, DMODEL);
    // 3. attention (tensor-core)
    attn_kernel<<<dim3(SEQ / ATQ, NHEAD, 2), 256, AT2_SMEM>>>(qkv, attn);
    // 4. x1 = x + attn @ wo + bo
    tgemm_kernel<EPI_BIAS_RES><<<dim3(DMODEL / 128, NTOK / 128), 128, GSMEM_BYTES>>>(
        attn, wor, bo, x, x1, NTOK, DMODEL, DMODEL);
    // 5. h = LN2(x1)
    ln_kernel<<<NTOK, 256>>>(x1, ln2_w, ln2_b, h);
    // 6. ff = gelu(h @ w1 + b1)
    tgemm_kernel<EPI_BIAS_GELU><<<dim3(DFF / 128, NTOK / 128), 128, GSMEM_BYTES>>>(
        h, w1r, b1, nullptr, ff, NTOK, DFF, DMODEL);
    // 7. out = x1 + ff @ w2 + b2
    tgemm_kernel<EPI_BIAS_RES><<<dim3(DMODEL / 128, NTOK / 128), 128, GSMEM_BYTES>>>(
        ff, w2r, b2, x1, out, NTOK, DMODEL, DFF);
}